// round 1
// baseline (speedup 1.0000x reference)
#include <cuda_runtime.h>

#define BN   4
#define LL   512
#define HH   768
#define HSZ  64
#define NOUT 16
#define NTOK (BN*LL)      // 2048
#define NP   131328       // L*(L+1)/2

// scratch (allocation-free rule: __device__ globals)
__device__ float g_q[NTOK*HSZ];       // 512 KB
__device__ float g_k[NTOK*HSZ];       // 512 KB
__device__ float g_A[NTOK*NOUT];      // 128 KB  (start-role contribution + bb)
__device__ float g_E[NTOK*NOUT];      // 128 KB  (end-role contribution)
__device__ float g_S[BN*LL*LL];       // 4 MB    (Gram matrices)

// ---------------------------------------------------------------------------
// Kernel 1: q = x@Wq+bq, k = x@Wk+bk  (fused as one 2048x128 GEMM, K=768),
// then A/E 16-dim projections straight from the shared-memory result tile.
// ---------------------------------------------------------------------------
__global__ __launch_bounds__(256) void proj_kernel(
    const float* __restrict__ x,
    const float* __restrict__ Wq, const float* __restrict__ bq,
    const float* __restrict__ Wk, const float* __restrict__ bk,
    const float* __restrict__ Wb, const float* __restrict__ bb)
{
    __shared__ float xs[16][65];     // [k][token]
    __shared__ float ws[16][128];    // [k][n]  n<64 -> Wq col, else Wk col
    __shared__ float sQK[64][128];   // result tile: [tokenLocal][q(64)|k(64)]

    const int tid = threadIdx.x;
    const int t0  = blockIdx.x * 64;           // 32 blocks of 64 tokens
    const int n0  = (tid & 15) * 8;            // 8 output cols per thread
    const int m0  = (tid >> 4) * 4;            // 4 tokens per thread

    float acc[4][8];
    #pragma unroll
    for (int i = 0; i < 4; i++)
        #pragma unroll
        for (int j = 0; j < 8; j++) acc[i][j] = 0.f;

    for (int kk = 0; kk < HH; kk += 16) {
        #pragma unroll
        for (int p = 0; p < 4; p++) {
            int e = tid + p * 256;
            int tok = e >> 4, d = e & 15;
            xs[d][tok] = x[(t0 + tok) * HH + kk + d];
        }
        #pragma unroll
        for (int p = 0; p < 8; p++) {
            int e = tid + p * 256;
            int n = e & 127, d = e >> 7;
            ws[d][n] = (n < 64) ? Wq[(kk + d) * HSZ + n]
                                : Wk[(kk + d) * HSZ + (n - 64)];
        }
        __syncthreads();
        #pragma unroll
        for (int kd = 0; kd < 16; kd++) {
            float a[4], w[8];
            #pragma unroll
            for (int i = 0; i < 4; i++) a[i] = xs[kd][m0 + i];
            #pragma unroll
            for (int j = 0; j < 8; j++) w[j] = ws[kd][n0 + j];
            #pragma unroll
            for (int i = 0; i < 4; i++)
                #pragma unroll
                for (int j = 0; j < 8; j++) acc[i][j] += a[i] * w[j];
        }
        __syncthreads();
    }

    // epilogue: bias, stash in shared + global q/k
    #pragma unroll
    for (int i = 0; i < 4; i++) {
        int tok = t0 + m0 + i;
        #pragma unroll
        for (int j = 0; j < 8; j++) {
            int n = n0 + j;
            float v = acc[i][j] + (n < 64 ? bq[n] : bk[n - 64]);
            sQK[m0 + i][n] = v;
            if (n < 64) g_q[tok * HSZ + n]        = v;
            else        g_k[tok * HSZ + (n - 64)] = v;
        }
    }
    __syncthreads();

    // A[s,o] = q[s]@Wb[0:64] + bb ;  E[e,o] = k[e]@(Wb[64:128]+Wb[192:256]) + q[e]@Wb[128:192]
    #pragma unroll
    for (int p = 0; p < 8; p++) {
        int e2   = tid + p * 256;
        int tokL = e2 >> 5;            // warp-uniform -> sQK reads broadcast
        int oo   = e2 & 31;
        int tok  = t0 + tokL;
        if (oo < 16) {
            int o = oo;
            float a = bb[o];
            #pragma unroll 8
            for (int h = 0; h < 64; h++)
                a += sQK[tokL][h] * Wb[h * NOUT + o];
            g_A[tok * NOUT + o] = a;
        } else {
            int o = oo - 16;
            float a = 0.f;
            #pragma unroll 8
            for (int h = 0; h < 64; h++) {
                a += sQK[tokL][64 + h] * (Wb[(64 + h) * NOUT + o] + Wb[(192 + h) * NOUT + o]);
                a += sQK[tokL][h]      *  Wb[(128 + h) * NOUT + o];
            }
            g_E[tok * NOUT + o] = a;
        }
    }
}

// ---------------------------------------------------------------------------
// Kernel 2: S[b] = Q[b] @ K[b]^T  (512x512, K=64, single pass).
// 64x64 tiles; tiles entirely below the diagonal are skipped.
// ---------------------------------------------------------------------------
__global__ __launch_bounds__(256) void score_kernel()
{
    const int bx = blockIdx.x;   // e tile
    const int by = blockIdx.y;   // s tile
    if (by > bx) return;         // fully below diagonal -> never read
    const int b  = blockIdx.z;

    __shared__ float qs[64][68]; // [h][s]  pad 68 -> 16B-aligned float4 rows
    __shared__ float ks[64][68]; // [h][e]

    const int tid = threadIdx.x;
    const float* qb = g_q + (b * LL + by * 64) * HSZ;
    const float* kb = g_k + (b * LL + bx * 64) * HSZ;

    #pragma unroll
    for (int p = 0; p < 16; p++) {
        int e = tid + p * 256;
        int r = e >> 6, h = e & 63;
        qs[h][r] = qb[r * HSZ + h];
        ks[h][r] = kb[r * HSZ + h];
    }
    __syncthreads();

    const int m0 = (tid >> 4) * 4;
    const int n0 = (tid & 15) * 4;
    float acc[4][4];
    #pragma unroll
    for (int i = 0; i < 4; i++)
        #pragma unroll
        for (int j = 0; j < 4; j++) acc[i][j] = 0.f;

    #pragma unroll
    for (int h = 0; h < 64; h++) {
        float4 a = *(const float4*)&qs[h][m0];
        float4 v = *(const float4*)&ks[h][n0];
        float am[4] = {a.x, a.y, a.z, a.w};
        float vn[4] = {v.x, v.y, v.z, v.w};
        #pragma unroll
        for (int i = 0; i < 4; i++)
            #pragma unroll
            for (int j = 0; j < 4; j++) acc[i][j] += am[i] * vn[j];
    }

    float* Sp = g_S + (size_t)b * LL * LL + (by * 64 + m0) * LL + bx * 64 + n0;
    #pragma unroll
    for (int i = 0; i < 4; i++) {
        float4 o = make_float4(acc[i][0], acc[i][1], acc[i][2], acc[i][3]);
        *(float4*)&Sp[i * LL] = o;
    }
}

// ---------------------------------------------------------------------------
// Kernel 3: scatter. One block per (b, s): pairs (s,e), e in [s, L).
// out[b, off(s)+(e-s), o] = S[b,s,e] + A[b,s,o] + E[b,e,o]
// Writes are fully coalesced (o is the fast index).
// ---------------------------------------------------------------------------
__global__ __launch_bounds__(256) void scatter_kernel(float* __restrict__ out)
{
    const int s = blockIdx.x;
    const int b = blockIdx.y;

    __shared__ float As[16];
    if (threadIdx.x < 16)
        As[threadIdx.x] = g_A[(b * LL + s) * NOUT + threadIdx.x];
    __syncthreads();

    const int nE   = LL - s;
    const int base = b * NP + s * LL - (s * (s - 1)) / 2;   // pair index of (s,s)
    const float* Srow = g_S + (size_t)b * LL * LL + (size_t)s * LL;
    const float* Eb   = g_E + b * LL * NOUT;
    float* op = out + (size_t)base * NOUT;

    const int total = nE * NOUT;
    for (int idx = threadIdx.x; idx < total; idx += 256) {
        int j = idx >> 4, o = idx & 15;
        int e = s + j;
        op[idx] = Srow[e] + As[o] + Eb[e * NOUT + o];
    }
}

extern "C" void kernel_launch(void* const* d_in, const int* in_sizes, int n_in,
                              void* d_out, int out_size)
{
    const float* x  = (const float*)d_in[0];
    const float* Wq = (const float*)d_in[1];
    const float* bq = (const float*)d_in[2];
    const float* Wk = (const float*)d_in[3];
    const float* bk = (const float*)d_in[4];
    const float* Wb = (const float*)d_in[5];
    const float* bb = (const float*)d_in[6];
    float* out = (float*)d_out;

    proj_kernel<<<32, 256>>>(x, Wq, bq, Wk, bk, Wb, bb);
    dim3 g2(LL / 64, LL / 64, BN);
    score_kernel<<<g2, 256>>>();
    dim3 g3(LL, BN);
    scatter_kernel<<<g3, 256>>>(out);
}

// round 2
// speedup vs baseline: 1.4612x; 1.4612x over previous
#include <cuda_runtime.h>

#define BN   4
#define LL   512
#define HH   768
#define HSZ  64
#define NOUT 16
#define NTOK (BN*LL)      // 2048
#define NP   131328       // L*(L+1)/2
#define KQ   192          // K quarter (768/4)

// scratch (allocation-free rule: __device__ globals)
__device__ float g_part[4*NTOK*128];  // 4 MB split-K partials [kq][tok][n]
__device__ float g_q[NTOK*HSZ];       // 512 KB
__device__ float g_k[NTOK*HSZ];       // 512 KB
__device__ float g_A[NTOK*NOUT];      // 128 KB (start-role contribution + bb)
__device__ float g_E[NTOK*NOUT];      // 128 KB (end-role contribution)
__device__ float g_S[BN*LL*LL];       // 4 MB   (Gram matrices)

// ---------------------------------------------------------------------------
// Kernel 1: split-K partial GEMM. out_partial[kq] = x[:, kq*192:(kq+1)*192] @ [Wq|Wk]
// Grid: 32 token-tiles (64 tokens) x 4 K-quarters = 128 blocks (one full wave).
// Per-thread 4x8 register tile, float4 shared loads.
// ---------------------------------------------------------------------------
__global__ __launch_bounds__(256) void proj_partial_kernel(
    const float* __restrict__ x,
    const float* __restrict__ Wq,
    const float* __restrict__ Wk)
{
    __shared__ float xs[16][68];     // [k][token]  (68 keeps float4 row alignment)
    __shared__ float ws[16][128];    // [k][n]  n<64 -> Wq col, else Wk col

    const int tid = threadIdx.x;
    const int tt  = blockIdx.x & 31;           // token tile
    const int kq  = blockIdx.x >> 5;           // K quarter
    const int t0  = tt * 64;
    const int k0  = kq * KQ;
    const int n0  = (tid & 15) * 8;            // 8 output cols per thread
    const int m0  = (tid >> 4) * 4;            // 4 tokens per thread

    float acc[4][8];
    #pragma unroll
    for (int i = 0; i < 4; i++)
        #pragma unroll
        for (int j = 0; j < 8; j++) acc[i][j] = 0.f;

    for (int kk = k0; kk < k0 + KQ; kk += 16) {
        #pragma unroll
        for (int p = 0; p < 4; p++) {
            int e = tid + p * 256;
            int tok = e >> 4, d = e & 15;
            xs[d][tok] = x[(t0 + tok) * HH + kk + d];
        }
        #pragma unroll
        for (int p = 0; p < 8; p++) {
            int e = tid + p * 256;
            int n = e & 127, d = e >> 7;
            ws[d][n] = (n < 64) ? Wq[(kk + d) * HSZ + n]
                                : Wk[(kk + d) * HSZ + (n - 64)];
        }
        __syncthreads();
        #pragma unroll
        for (int kd = 0; kd < 16; kd++) {
            float4 av = *(const float4*)&xs[kd][m0];
            float4 w0 = *(const float4*)&ws[kd][n0];
            float4 w1 = *(const float4*)&ws[kd][n0 + 4];
            float am[4] = {av.x, av.y, av.z, av.w};
            float wn[8] = {w0.x, w0.y, w0.z, w0.w, w1.x, w1.y, w1.z, w1.w};
            #pragma unroll
            for (int i = 0; i < 4; i++)
                #pragma unroll
                for (int j = 0; j < 8; j++) acc[i][j] += am[i] * wn[j];
        }
        __syncthreads();
    }

    // write partials (no bias here) — coalesced float4 stores
    float* gp = g_part + ((size_t)kq * NTOK + t0 + m0) * 128 + n0;
    #pragma unroll
    for (int i = 0; i < 4; i++) {
        *(float4*)&gp[i * 128]     = make_float4(acc[i][0], acc[i][1], acc[i][2], acc[i][3]);
        *(float4*)&gp[i * 128 + 4] = make_float4(acc[i][4], acc[i][5], acc[i][6], acc[i][7]);
    }
}

// ---------------------------------------------------------------------------
// Kernel 2: reduce split-K partials + bias -> g_q/g_k, and compute A/E tables
// with Wb staged in shared memory.
// A[s,o] = q[s]@Wb[0:64] + bb
// E[e,o] = k[e]@(Wb[64:128]+Wb[192:256]) + q[e]@Wb[128:192]
// Grid: 64 blocks x 32 tokens.
// ---------------------------------------------------------------------------
__global__ __launch_bounds__(256) void reduce_ae_kernel(
    const float* __restrict__ bq, const float* __restrict__ bk,
    const float* __restrict__ bb, const float* __restrict__ Wb)
{
    __shared__ float Wbs[256 * NOUT];   // 16 KB
    __shared__ float sQK[32][128];      // 16 KB
    __shared__ float bbs[NOUT];

    const int tid = threadIdx.x;
    const int t0  = blockIdx.x * 32;

    #pragma unroll
    for (int p = 0; p < 16; p++)
        Wbs[tid + p * 256] = Wb[tid + p * 256];
    if (tid < NOUT) bbs[tid] = bb[tid];

    #pragma unroll
    for (int p = 0; p < 16; p++) {
        int e = tid + p * 256;
        int tok = e >> 7, n = e & 127;
        size_t gi = (size_t)(t0 + tok) * 128 + n;
        float v = g_part[gi]
                + g_part[(size_t)NTOK * 128 + gi]
                + g_part[(size_t)2 * NTOK * 128 + gi]
                + g_part[(size_t)3 * NTOK * 128 + gi];
        v += (n < 64) ? bq[n] : bk[n - 64];
        sQK[tok][n] = v;
        int tok_g = t0 + tok;
        if (n < 64) g_q[tok_g * HSZ + n]        = v;
        else        g_k[tok_g * HSZ + (n - 64)] = v;
    }
    __syncthreads();

    #pragma unroll
    for (int p = 0; p < 4; p++) {
        int e2   = tid + p * 256;
        int tokL = e2 >> 5;            // warp-uniform -> sQK broadcast reads
        int oo   = e2 & 31;
        int tok  = t0 + tokL;
        if (oo < NOUT) {
            int o = oo;
            float a = bbs[o];
            #pragma unroll 8
            for (int h = 0; h < 64; h++)
                a += sQK[tokL][h] * Wbs[h * NOUT + o];
            g_A[tok * NOUT + o] = a;
        } else {
            int o = oo - NOUT;
            float a = 0.f;
            #pragma unroll 8
            for (int h = 0; h < 64; h++) {
                a += sQK[tokL][64 + h] * (Wbs[(64 + h) * NOUT + o] + Wbs[(192 + h) * NOUT + o]);
                a += sQK[tokL][h]      *  Wbs[(128 + h) * NOUT + o];
            }
            g_E[tok * NOUT + o] = a;
        }
    }
}

// ---------------------------------------------------------------------------
// Kernel 3: S[b] = Q[b] @ K[b]^T  (512x512, K=64, single pass).
// 64x64 tiles; tiles entirely below the diagonal are skipped.
// ---------------------------------------------------------------------------
__global__ __launch_bounds__(256) void score_kernel()
{
    const int bx = blockIdx.x;   // e tile
    const int by = blockIdx.y;   // s tile
    if (by > bx) return;         // fully below diagonal -> never read
    const int b  = blockIdx.z;

    __shared__ float qs[64][68]; // [h][s]
    __shared__ float ks[64][68]; // [h][e]

    const int tid = threadIdx.x;
    const float* qb = g_q + (b * LL + by * 64) * HSZ;
    const float* kb = g_k + (b * LL + bx * 64) * HSZ;

    #pragma unroll
    for (int p = 0; p < 16; p++) {
        int e = tid + p * 256;
        int r = e >> 6, h = e & 63;
        qs[h][r] = qb[r * HSZ + h];
        ks[h][r] = kb[r * HSZ + h];
    }
    __syncthreads();

    const int m0 = (tid >> 4) * 4;
    const int n0 = (tid & 15) * 4;
    float acc[4][4];
    #pragma unroll
    for (int i = 0; i < 4; i++)
        #pragma unroll
        for (int j = 0; j < 4; j++) acc[i][j] = 0.f;

    #pragma unroll
    for (int h = 0; h < 64; h++) {
        float4 a = *(const float4*)&qs[h][m0];
        float4 v = *(const float4*)&ks[h][n0];
        float am[4] = {a.x, a.y, a.z, a.w};
        float vn[4] = {v.x, v.y, v.z, v.w};
        #pragma unroll
        for (int i = 0; i < 4; i++)
            #pragma unroll
            for (int j = 0; j < 4; j++) acc[i][j] += am[i] * vn[j];
    }

    float* Sp = g_S + (size_t)b * LL * LL + (by * 64 + m0) * LL + bx * 64 + n0;
    #pragma unroll
    for (int i = 0; i < 4; i++)
        *(float4*)&Sp[i * LL] = make_float4(acc[i][0], acc[i][1], acc[i][2], acc[i][3]);
}

// ---------------------------------------------------------------------------
// Kernel 4: scatter. One block per (b, s): pairs (s,e), e in [s, L).
// out[b, off(s)+(e-s), o] = S[b,s,e] + A[b,s,o] + E[b,e,o]
// ---------------------------------------------------------------------------
__global__ __launch_bounds__(256) void scatter_kernel(float* __restrict__ out)
{
    const int s = blockIdx.x;
    const int b = blockIdx.y;

    __shared__ float As[NOUT];
    if (threadIdx.x < NOUT)
        As[threadIdx.x] = g_A[(b * LL + s) * NOUT + threadIdx.x];
    __syncthreads();

    const int nE   = LL - s;
    const int base = b * NP + s * LL - (s * (s - 1)) / 2;   // pair index of (s,s)
    const float* Srow = g_S + (size_t)b * LL * LL + (size_t)s * LL;
    const float* Eb   = g_E + b * LL * NOUT;
    float* op = out + (size_t)base * NOUT;

    const int total = nE * NOUT;
    for (int idx = threadIdx.x; idx < total; idx += 256) {
        int j = idx >> 4, o = idx & 15;
        int e = s + j;
        op[idx] = Srow[e] + As[o] + Eb[e * NOUT + o];
    }
}

extern "C" void kernel_launch(void* const* d_in, const int* in_sizes, int n_in,
                              void* d_out, int out_size)
{
    const float* x  = (const float*)d_in[0];
    const float* Wq = (const float*)d_in[1];
    const float* bq = (const float*)d_in[2];
    const float* Wk = (const float*)d_in[3];
    const float* bk = (const float*)d_in[4];
    const float* Wb = (const float*)d_in[5];
    const float* bb = (const float*)d_in[6];
    float* out = (float*)d_out;

    proj_partial_kernel<<<128, 256>>>(x, Wq, Wk);
    reduce_ae_kernel<<<64, 256>>>(bq, bk, bb, Wb);
    dim3 g2(LL / 64, LL / 64, BN);
    score_kernel<<<g2, 256>>>();
    dim3 g3(LL, BN);
    scatter_kernel<<<g3, 256>>>(out);
}

// round 3
// speedup vs baseline: 2.7477x; 1.8805x over previous
#include <cuda_runtime.h>

#define BN   4
#define LL   512
#define HH   768
#define HSZ  64
#define NOUT 16
#define NTOK (BN*LL)      // 2048
#define NP   131328       // L*(L+1)/2
#define NKQ  16           // split-K factor
#define KQ   (HH/NKQ)     // 48

// scratch (allocation-free rule: __device__ globals)
__device__ float g_part[NKQ*NTOK*128]; // 16 MB split-K partials [kq][tok][n]
__device__ float g_q[NTOK*HSZ];        // 512 KB
__device__ float g_k[NTOK*HSZ];        // 512 KB
__device__ float g_A[NTOK*NOUT];       // 128 KB (start-role contribution + bb)
__device__ float g_E[NTOK*NOUT];       // 128 KB (end-role contribution)
__device__ float g_S[BN*LL*LL];        // 4 MB   (Gram matrices)

// ---------------------------------------------------------------------------
// Kernel 1: split-K partial GEMM. 16 token-tiles (128 tok) x 16 K-slices (48)
// = 256 blocks -> 2 blocks/SM, 16 warps for latency hiding.
// 8x8 per-thread register tile; LDS and FMA pipes balanced (64 FMA : 64 B).
// ---------------------------------------------------------------------------
__global__ __launch_bounds__(256, 2) void proj_partial_kernel(
    const float* __restrict__ x,
    const float* __restrict__ Wq,
    const float* __restrict__ Wk)
{
    __shared__ float xs[16][132];    // [k][token]  (132: float4-aligned rows)
    __shared__ float ws[16][128];    // [k][n] n<64 -> Wq col else Wk col

    const int tid = threadIdx.x;
    const int tt  = blockIdx.x & 15;           // token tile (128 tokens)
    const int kq  = blockIdx.x >> 4;           // K slice
    const int t0  = tt * 128;
    const int k0  = kq * KQ;
    const int n0  = (tid & 15) * 8;
    const int m0  = (tid >> 4) * 8;

    float acc[8][8];
    #pragma unroll
    for (int i = 0; i < 8; i++)
        #pragma unroll
        for (int j = 0; j < 8; j++) acc[i][j] = 0.f;

    for (int kk = k0; kk < k0 + KQ; kk += 16) {
        #pragma unroll
        for (int p = 0; p < 8; p++) {
            int e = tid + p * 256;
            int tok = e >> 4, d = e & 15;
            xs[d][tok] = x[(t0 + tok) * HH + kk + d];
        }
        #pragma unroll
        for (int p = 0; p < 8; p++) {
            int e = tid + p * 256;
            int n = e & 127, d = e >> 7;
            ws[d][n] = (n < 64) ? Wq[(kk + d) * HSZ + n]
                                : Wk[(kk + d) * HSZ + (n - 64)];
        }
        __syncthreads();
        #pragma unroll
        for (int kd = 0; kd < 16; kd++) {
            float4 a0 = *(const float4*)&xs[kd][m0];
            float4 a1 = *(const float4*)&xs[kd][m0 + 4];
            float4 w0 = *(const float4*)&ws[kd][n0];
            float4 w1 = *(const float4*)&ws[kd][n0 + 4];
            float am[8] = {a0.x, a0.y, a0.z, a0.w, a1.x, a1.y, a1.z, a1.w};
            float wn[8] = {w0.x, w0.y, w0.z, w0.w, w1.x, w1.y, w1.z, w1.w};
            #pragma unroll
            for (int i = 0; i < 8; i++)
                #pragma unroll
                for (int j = 0; j < 8; j++) acc[i][j] += am[i] * wn[j];
        }
        __syncthreads();
    }

    #pragma unroll
    for (int i = 0; i < 8; i++) {
        float* gp = g_part + ((size_t)kq * NTOK + t0 + m0 + i) * 128 + n0;
        *(float4*)&gp[0] = make_float4(acc[i][0], acc[i][1], acc[i][2], acc[i][3]);
        *(float4*)&gp[4] = make_float4(acc[i][4], acc[i][5], acc[i][6], acc[i][7]);
    }
}

// ---------------------------------------------------------------------------
// Kernel 2: reduce split-K partials + bias -> g_q/g_k, then A/E tables with
// Wb staged in shared. 64 blocks x 32 tokens. All partial traffic is float4.
// A[s,o] = q[s]@Wb[0:64] + bb
// E[e,o] = k[e]@(Wb[64:128]+Wb[192:256]) + q[e]@Wb[128:192]
// ---------------------------------------------------------------------------
__global__ __launch_bounds__(256) void reduce_ae_kernel(
    const float* __restrict__ bq, const float* __restrict__ bk,
    const float* __restrict__ bb, const float* __restrict__ Wb)
{
    __shared__ float Wbs[256 * NOUT];   // 16 KB
    __shared__ float sQK[32][132];      // 16.5 KB
    __shared__ float bbs[NOUT];
    __shared__ float bqs[HSZ], bks[HSZ];

    const int tid = threadIdx.x;
    const int t0  = blockIdx.x * 32;

    #pragma unroll
    for (int p = 0; p < 16; p++)
        Wbs[tid + p * 256] = Wb[tid + p * 256];
    if (tid < NOUT) bbs[tid] = bb[tid];
    if (tid < HSZ)  { bqs[tid] = bq[tid]; bks[tid] = bk[tid]; }
    __syncthreads();

    const float4* gp4 = (const float4*)g_part;
    #pragma unroll
    for (int p = 0; p < 4; p++) {
        int e  = tid + p * 256;            // 1024 = 32 tok x 32 float4
        int tok = e >> 5, n4 = e & 31;
        size_t gi = (size_t)(t0 + tok) * 32 + n4;
        float4 v = make_float4(0.f, 0.f, 0.f, 0.f);
        #pragma unroll
        for (int q = 0; q < NKQ; q++) {
            float4 pv = gp4[(size_t)q * NTOK * 32 + gi];
            v.x += pv.x; v.y += pv.y; v.z += pv.z; v.w += pv.w;
        }
        int n = n4 * 4;
        if (n < 64) { v.x += bqs[n]; v.y += bqs[n+1]; v.z += bqs[n+2]; v.w += bqs[n+3]; }
        else        { v.x += bks[n-64]; v.y += bks[n-63]; v.z += bks[n-62]; v.w += bks[n-61]; }
        *(float4*)&sQK[tok][n] = v;
        int tok_g = t0 + tok;
        if (n4 < 16) ((float4*)(g_q + tok_g * HSZ))[n4]      = v;
        else         ((float4*)(g_k + tok_g * HSZ))[n4 - 16] = v;
    }
    __syncthreads();

    #pragma unroll
    for (int p = 0; p < 4; p++) {
        int e2   = tid + p * 256;
        int tokL = e2 >> 5;            // warp-uniform -> sQK broadcast reads
        int oo   = e2 & 31;
        int tok  = t0 + tokL;
        if (oo < NOUT) {
            int o = oo;
            float a = bbs[o];
            #pragma unroll 8
            for (int h = 0; h < 64; h++)
                a += sQK[tokL][h] * Wbs[h * NOUT + o];
            g_A[tok * NOUT + o] = a;
        } else {
            int o = oo - NOUT;
            float a = 0.f;
            #pragma unroll 8
            for (int h = 0; h < 64; h++) {
                a += sQK[tokL][64 + h] * (Wbs[(64 + h) * NOUT + o] + Wbs[(192 + h) * NOUT + o]);
                a += sQK[tokL][h]      *  Wbs[(128 + h) * NOUT + o];
            }
            g_E[tok * NOUT + o] = a;
        }
    }
}

// ---------------------------------------------------------------------------
// Kernel 3: S[b] = Q[b] @ K[b]^T  (512x512, K=64). 64x64 tiles; below-diagonal
// tiles early-exit.
// ---------------------------------------------------------------------------
__global__ __launch_bounds__(256) void score_kernel()
{
    const int bx = blockIdx.x;   // e tile
    const int by = blockIdx.y;   // s tile
    if (by > bx) return;
    const int b  = blockIdx.z;

    __shared__ float qs[64][68]; // [h][s]
    __shared__ float ks[64][68]; // [h][e]

    const int tid = threadIdx.x;
    const float* qb = g_q + (b * LL + by * 64) * HSZ;
    const float* kb = g_k + (b * LL + bx * 64) * HSZ;

    #pragma unroll
    for (int p = 0; p < 16; p++) {
        int e = tid + p * 256;
        int r = e >> 6, h = e & 63;
        qs[h][r] = qb[r * HSZ + h];
        ks[h][r] = kb[r * HSZ + h];
    }
    __syncthreads();

    const int m0 = (tid >> 4) * 4;
    const int n0 = (tid & 15) * 4;
    float acc[4][4];
    #pragma unroll
    for (int i = 0; i < 4; i++)
        #pragma unroll
        for (int j = 0; j < 4; j++) acc[i][j] = 0.f;

    #pragma unroll
    for (int h = 0; h < 64; h++) {
        float4 a = *(const float4*)&qs[h][m0];
        float4 v = *(const float4*)&ks[h][n0];
        float am[4] = {a.x, a.y, a.z, a.w};
        float vn[4] = {v.x, v.y, v.z, v.w};
        #pragma unroll
        for (int i = 0; i < 4; i++)
            #pragma unroll
            for (int j = 0; j < 4; j++) acc[i][j] += am[i] * vn[j];
    }

    float* Sp = g_S + (size_t)b * LL * LL + (by * 64 + m0) * LL + bx * 64 + n0;
    #pragma unroll
    for (int i = 0; i < 4; i++)
        *(float4*)&Sp[i * LL] = make_float4(acc[i][0], acc[i][1], acc[i][2], acc[i][3]);
}

// ---------------------------------------------------------------------------
// Kernel 4: scatter, fully float4. One block per (b, s).
// out[b, off(s)+j, :] = S[b,s,s+j] + A[b,s,:] + E[b,s+j,:]
// ---------------------------------------------------------------------------
__global__ __launch_bounds__(256) void scatter_kernel(float* __restrict__ out)
{
    const int s = blockIdx.x;
    const int b = blockIdx.y;

    __shared__ float  Ss[LL];      // S row for e = s..511, indexed by j
    __shared__ float4 As4[4];

    const int nE = LL - s;
    const float* Srow = g_S + (size_t)b * LL * LL + (size_t)s * LL + s;
    for (int i = threadIdx.x; i < nE; i += 256) Ss[i] = Srow[i];
    if (threadIdx.x < 4)
        As4[threadIdx.x] = ((const float4*)(g_A + (b * LL + s) * NOUT))[threadIdx.x];
    __syncthreads();

    const int base = b * NP + s * LL - (s * (s - 1)) / 2;   // pair index of (s,s)
    const float4* E4   = (const float4*)(g_E + b * LL * NOUT) + (size_t)s * 4;
    float4*       out4 = (float4*)(out + (size_t)base * NOUT);

    const int total4 = nE * 4;
    for (int idx = threadIdx.x; idx < total4; idx += 256) {
        int j = idx >> 2, oq = idx & 3;
        float4 ev = E4[idx];
        float4 av = As4[oq];
        float  sv = Ss[j];
        out4[idx] = make_float4(sv + av.x + ev.x, sv + av.y + ev.y,
                                sv + av.z + ev.z, sv + av.w + ev.w);
    }
}

extern "C" void kernel_launch(void* const* d_in, const int* in_sizes, int n_in,
                              void* d_out, int out_size)
{
    const float* x  = (const float*)d_in[0];
    const float* Wq = (const float*)d_in[1];
    const float* bq = (const float*)d_in[2];
    const float* Wk = (const float*)d_in[3];
    const float* bk = (const float*)d_in[4];
    const float* Wb = (const float*)d_in[5];
    const float* bb = (const float*)d_in[6];
    float* out = (float*)d_out;

    proj_partial_kernel<<<256, 256>>>(x, Wq, Wk);
    reduce_ae_kernel<<<64, 256>>>(bq, bk, bb, Wb);
    dim3 g2(LL / 64, LL / 64, BN);
    score_kernel<<<g2, 256>>>();
    dim3 g3(LL, BN);
    scatter_kernel<<<g3, 256>>>(out);
}